// round 5
// baseline (speedup 1.0000x reference)
#include <cuda_runtime.h>
#include <cuda_bf16.h>
#include <cstdint>
#include <math.h>

// Problem constants
#define BB   2
#define SS   2048
#define DD   768
#define HH   12
#define HDIM 64
#define HALFW 64
#define NEGV -1000000000.0f

// ---------------------------------------------------------------------------
// Scratch (no cudaMalloc allowed)
// ---------------------------------------------------------------------------
__device__ float g_qkv[BB * SS * 3 * DD];            // fp32 qkv  (4096 x 2304)
__device__ float g_att[BB * SS * DD];                // fp32 attn out (4096 x 768)
__device__ __nv_bfloat16 g_xhi[BB * SS * DD];        // x split
__device__ __nv_bfloat16 g_xlo[BB * SS * DD];
__device__ __nv_bfloat16 g_wqh[3 * DD * DD];         // Wqkv^T split (2304 x 768)
__device__ __nv_bfloat16 g_wql[3 * DD * DD];
__device__ __nv_bfloat16 g_woh[DD * DD];             // Wo^T split (768 x 768)
__device__ __nv_bfloat16 g_wol[DD * DD];
__device__ __nv_bfloat16 g_ahi[BB * SS * DD];        // att split
__device__ __nv_bfloat16 g_alo[BB * SS * DD];

// ---------------------------------------------------------------------------
// Split / transpose-split conversion kernels
// ---------------------------------------------------------------------------
__global__ __launch_bounds__(256) void split_kernel(
    const float* __restrict__ in, __nv_bfloat16* __restrict__ hi,
    __nv_bfloat16* __restrict__ lo, int n)
{
    int i = blockIdx.x * 256 + threadIdx.x;
    if (i < n) {
        float v = in[i];
        __nv_bfloat16 h = __float2bfloat16(v);
        hi[i] = h;
        lo[i] = __float2bfloat16(v - __bfloat162float(h));
    }
}

// in[K x N] -> hiT/loT [N x K]
__global__ __launch_bounds__(256) void splitT_kernel(
    const float* __restrict__ in, __nv_bfloat16* __restrict__ hiT,
    __nv_bfloat16* __restrict__ loT, int K, int N)
{
    __shared__ float t[32][33];
    const int k0 = blockIdx.y * 32, n0 = blockIdx.x * 32;
    const int tx = threadIdx.x, ty = threadIdx.y;   // 32 x 8
    #pragma unroll
    for (int i = 0; i < 32; i += 8)
        t[ty + i][tx] = in[(size_t)(k0 + ty + i) * N + n0 + tx];
    __syncthreads();
    #pragma unroll
    for (int i = 0; i < 32; i += 8) {
        float v = t[tx][ty + i];
        __nv_bfloat16 h = __float2bfloat16(v);
        size_t o = (size_t)(n0 + ty + i) * K + k0 + tx;
        hiT[o] = h;
        loT[o] = __float2bfloat16(v - __bfloat162float(h));
    }
}

// ---------------------------------------------------------------------------
// bf16x3 mma.sync GEMM with cp.async double buffering + ldmatrix.
// C[M,N] = A[M,K] @ Bt[N,K]^T, fp32 accumulate.
// Block tile 128x128x32, 8 warps (2m x 4n), warp tile 64x32 via m16n8k16.
// M%128==0, N%128==0, K%32==0.
// ---------------------------------------------------------------------------
#define SMS 40                                  // smem row stride, bf16 elems
#define TILE_BYTES (128 * SMS * 2)              // 10240
#define STAGE_BYTES (4 * TILE_BYTES)            // 40960 (Ah, Al, Bh, Bl)
#define GEMM_SMEM (2 * STAGE_BYTES)             // 81920

__device__ __forceinline__ uint32_t smem_u32(const void* p) {
    uint32_t a;
    asm("{ .reg .u64 t; cvta.to.shared.u64 t, %1; cvt.u32.u64 %0, t; }"
        : "=r"(a) : "l"(p));
    return a;
}

__device__ __forceinline__ void cp_async16(uint32_t dst, const void* src) {
    asm volatile("cp.async.cg.shared.global [%0], [%1], 16;" :: "r"(dst), "l"(src));
}

#define CP_COMMIT() asm volatile("cp.async.commit_group;" ::: "memory")
#define CP_WAIT1()  asm volatile("cp.async.wait_group 1;" ::: "memory")

#define LDSM_X4(r0, r1, r2, r3, addr) \
    asm volatile("ldmatrix.sync.aligned.m8n8.x4.shared.b16 {%0,%1,%2,%3}, [%4];" \
                 : "=r"(r0), "=r"(r1), "=r"(r2), "=r"(r3) : "r"(addr))
#define LDSM_X2(r0, r1, addr) \
    asm volatile("ldmatrix.sync.aligned.m8n8.x2.shared.b16 {%0,%1}, [%2];" \
                 : "=r"(r0), "=r"(r1) : "r"(addr))

__device__ __forceinline__ void mma16816(float* c, const uint32_t* a, const uint32_t* b)
{
    asm volatile(
        "mma.sync.aligned.m16n8k16.row.col.f32.bf16.bf16.f32 "
        "{%0,%1,%2,%3}, {%4,%5,%6,%7}, {%8,%9}, {%0,%1,%2,%3};"
        : "+f"(c[0]), "+f"(c[1]), "+f"(c[2]), "+f"(c[3])
        : "r"(a[0]), "r"(a[1]), "r"(a[2]), "r"(a[3]), "r"(b[0]), "r"(b[1]));
}

__global__ __launch_bounds__(256) void gemm_bf16x3_kernel(
    const __nv_bfloat16* __restrict__ Ahi, const __nv_bfloat16* __restrict__ Alo,
    const __nv_bfloat16* __restrict__ Bthi, const __nv_bfloat16* __restrict__ Btlo,
    float* __restrict__ C, int M, int N, int K)
{
    extern __shared__ __align__(128) char smem[];
    const uint32_t smem_base = smem_u32(smem);

    const int tid = threadIdx.x;
    const int wid = tid >> 5, lane = tid & 31;
    const int g = lane >> 2, tg = lane & 3;
    const int wm = wid >> 2, wn = wid & 3;        // 2 x 4 warp grid
    const int mbase = wm * 64, nbase = wn * 32;
    const int bm = blockIdx.y * 128, bn = blockIdx.x * 128;

    const __nv_bfloat16* srcs[4] = {
        Ahi + (size_t)bm * K, Alo + (size_t)bm * K,
        Bthi + (size_t)bn * K, Btlo + (size_t)bn * K };

    const int niter = K >> 5;

    // global/smem staging coords: per tile 2 chunks/thread (rows lr0, lr0+64)
    const int lr0 = tid >> 2, lq = tid & 3;
    const uint32_t st_off = (uint32_t)(lr0 * SMS + lq * 8) * 2;

    // ldmatrix lane address components
    const uint32_t a_lane = (uint32_t)((lane & 15) * (SMS * 2) + ((lane >> 4) << 4));
    const uint32_t b_lane = (uint32_t)((lane & 7) * (SMS * 2) + (((lane >> 3) & 1) << 4));

    float acc[4][4][4];
    #pragma unroll
    for (int i = 0; i < 4; i++)
        #pragma unroll
        for (int j = 0; j < 4; j++)
            #pragma unroll
            for (int c = 0; c < 4; c++) acc[i][j][c] = 0.f;

    // ---- prologue: stages 0 and 1 ----
    #pragma unroll
    for (int p = 0; p < 2; p++) {
        if (p < niter) {
            const int k0 = p << 5;
            const uint32_t sb = smem_base + (uint32_t)p * STAGE_BYTES;
            #pragma unroll
            for (int t = 0; t < 4; t++) {
                const __nv_bfloat16* s = srcs[t] + k0 + lq * 8;
                uint32_t d = sb + (uint32_t)t * TILE_BYTES + st_off;
                cp_async16(d, s + (size_t)lr0 * K);
                cp_async16(d + 64 * SMS * 2, s + (size_t)(lr0 + 64) * K);
            }
        }
        CP_COMMIT();
    }

    for (int it = 0; it < niter; it++) {
        CP_WAIT1();
        __syncthreads();

        const uint32_t sb = smem_base + (uint32_t)(it & 1) * STAGE_BYTES;
        const uint32_t aAh = sb + a_lane;
        const uint32_t aAl = sb + TILE_BYTES + a_lane;
        const uint32_t aBh = sb + 2 * TILE_BYTES + b_lane;
        const uint32_t aBl = sb + 3 * TILE_BYTES + b_lane;

        #pragma unroll
        for (int kk = 0; kk < 32; kk += 16) {
            uint32_t ah[4][4], al[4][4], bh[4][2], bl[4][2];
            #pragma unroll
            for (int mt = 0; mt < 4; mt++) {
                const uint32_t ro = (uint32_t)((mbase + mt * 16) * (SMS * 2) + kk * 2);
                LDSM_X4(ah[mt][0], ah[mt][1], ah[mt][2], ah[mt][3], aAh + ro);
                LDSM_X4(al[mt][0], al[mt][1], al[mt][2], al[mt][3], aAl + ro);
            }
            #pragma unroll
            for (int nt = 0; nt < 4; nt++) {
                const uint32_t ro = (uint32_t)((nbase + nt * 8) * (SMS * 2) + kk * 2);
                LDSM_X2(bh[nt][0], bh[nt][1], aBh + ro);
                LDSM_X2(bl[nt][0], bl[nt][1], aBl + ro);
            }
            #pragma unroll
            for (int mt = 0; mt < 4; mt++)
                #pragma unroll
                for (int nt = 0; nt < 4; nt++)
                    mma16816(acc[mt][nt], ah[mt], bh[nt]);
            #pragma unroll
            for (int mt = 0; mt < 4; mt++)
                #pragma unroll
                for (int nt = 0; nt < 4; nt++)
                    mma16816(acc[mt][nt], ah[mt], bl[nt]);
            #pragma unroll
            for (int mt = 0; mt < 4; mt++)
                #pragma unroll
                for (int nt = 0; nt < 4; nt++)
                    mma16816(acc[mt][nt], al[mt], bh[nt]);
        }
        __syncthreads();

        // issue stage it+2 into the buffer just consumed
        const int nx = it + 2;
        if (nx < niter) {
            const int k0 = nx << 5;
            const uint32_t db = smem_base + (uint32_t)(nx & 1) * STAGE_BYTES;
            #pragma unroll
            for (int t = 0; t < 4; t++) {
                const __nv_bfloat16* s = srcs[t] + k0 + lq * 8;
                uint32_t d = db + (uint32_t)t * TILE_BYTES + st_off;
                cp_async16(d, s + (size_t)lr0 * K);
                cp_async16(d + 64 * SMS * 2, s + (size_t)(lr0 + 64) * K);
            }
        }
        CP_COMMIT();
    }

    // Epilogue: direct fp32 stores (float2 per fragment half)
    #pragma unroll
    for (int mt = 0; mt < 4; mt++) {
        #pragma unroll
        for (int nt = 0; nt < 4; nt++) {
            const int row = bm + mbase + mt * 16 + g;
            const int col = bn + nbase + nt * 8 + tg * 2;
            float2 v0; v0.x = acc[mt][nt][0]; v0.y = acc[mt][nt][1];
            float2 v1; v1.x = acc[mt][nt][2]; v1.y = acc[mt][nt][3];
            *(float2*)&C[(size_t)row * N + col] = v0;
            *(float2*)&C[(size_t)(row + 8) * N + col] = v1;
        }
    }
}

// ---------------------------------------------------------------------------
// Sliding-window attention (unchanged)
// ---------------------------------------------------------------------------
__global__ __launch_bounds__(256) void attn_kernel(
    const float* __restrict__ qkv, const float* __restrict__ pmask,
    float* __restrict__ out)
{
    constexpr int QC = 32, KMAX = 160, KPAD = 161;
    extern __shared__ float sm[];
    float* Qs = sm;
    float* Ks = Qs + QC * HDIM;
    float* Vs = Ks + HDIM * KPAD;
    float* Ss = Vs + KMAX * HDIM;
    float* Pn = Ss + QC * KMAX;

    const int chunk = blockIdx.x, h = blockIdx.y, b = blockIdx.z;
    const int qbase = chunk * QC;
    const int k0   = max(0, qbase - HALFW);
    const int kend = min(SS, qbase + QC + HALFW);
    const int kN   = kend - k0;
    const int tid  = threadIdx.x;

    for (int idx = tid; idx < QC * HDIM; idx += 256) {
        int q = idx >> 6, d = idx & 63;
        Qs[q * HDIM + d] = qkv[((size_t)(b * SS + qbase + q)) * (3 * DD) + h * HDIM + d];
    }
    for (int idx = tid; idx < kN * HDIM; idx += 256) {
        int k = idx >> 6, d = idx & 63;
        size_t base = ((size_t)(b * SS + k0 + k)) * (3 * DD) + h * HDIM + d;
        Ks[d * KPAD + k] = qkv[base + DD];
        Vs[k * HDIM + d] = qkv[base + 2 * DD];
    }
    for (int k = tid; k < kN; k += 256)
        Pn[k] = (1.0f - pmask[b * SS + k0 + k]) * NEGV;
    __syncthreads();

    const int warp = tid >> 5, lane = tid & 31;
    const int qrow = warp * 4;

    float acc[4][5];
    #pragma unroll
    for (int i = 0; i < 4; i++)
        #pragma unroll
        for (int j = 0; j < 5; j++) acc[i][j] = 0.f;

    #pragma unroll 4
    for (int d = 0; d < HDIM; d++) {
        float aq[4];
        #pragma unroll
        for (int i = 0; i < 4; i++) aq[i] = Qs[(qrow + i) * HDIM + d];
        float kv[5];
        #pragma unroll
        for (int j = 0; j < 5; j++) kv[j] = Ks[d * KPAD + lane * 5 + j];
        #pragma unroll
        for (int i = 0; i < 4; i++)
            #pragma unroll
            for (int j = 0; j < 5; j++)
                acc[i][j] = fmaf(aq[i], kv[j], acc[i][j]);
    }

    const float scale = 0.125f;
    #pragma unroll
    for (int i = 0; i < 4; i++) {
        int gq = qbase + qrow + i;
        #pragma unroll
        for (int j = 0; j < 5; j++) {
            int k = lane * 5 + j;
            if (k < kN) {
                int gk = k0 + k;
                int dd = gq - gk; if (dd < 0) dd = -dd;
                float s = (dd <= HALFW) ? (acc[i][j] * scale + Pn[k]) : -1e30f;
                Ss[(qrow + i) * KMAX + k] = s;
            }
        }
    }
    __syncwarp();

    #pragma unroll
    for (int i = 0; i < 4; i++) {
        float* row = &Ss[(qrow + i) * KMAX];
        float m = -1e30f;
        for (int k = lane; k < kN; k += 32) m = fmaxf(m, row[k]);
        #pragma unroll
        for (int o = 16; o; o >>= 1) m = fmaxf(m, __shfl_xor_sync(0xffffffffu, m, o));
        float sum = 0.f;
        for (int k = lane; k < kN; k += 32) {
            float e = __expf(row[k] - m);
            row[k] = e;
            sum += e;
        }
        #pragma unroll
        for (int o = 16; o; o >>= 1) sum += __shfl_xor_sync(0xffffffffu, sum, o);
        float inv = 1.f / sum;
        for (int k = lane; k < kN; k += 32) row[k] *= inv;
    }
    __syncwarp();

    float o[4][2];
    #pragma unroll
    for (int i = 0; i < 4; i++) { o[i][0] = 0.f; o[i][1] = 0.f; }
    const int d0 = lane * 2;
    for (int k = 0; k < kN; k++) {
        float2 v = *(const float2*)&Vs[k * HDIM + d0];
        #pragma unroll
        for (int i = 0; i < 4; i++) {
            float p = Ss[(qrow + i) * KMAX + k];
            o[i][0] = fmaf(p, v.x, o[i][0]);
            o[i][1] = fmaf(p, v.y, o[i][1]);
        }
    }
    #pragma unroll
    for (int i = 0; i < 4; i++) {
        int gq = qbase + qrow + i;
        float2 r; r.x = o[i][0]; r.y = o[i][1];
        *(float2*)&out[((size_t)(b * SS + gq)) * DD + h * HDIM + d0] = r;
    }
}

// ---------------------------------------------------------------------------
extern "C" void kernel_launch(void* const* d_in, const int* in_sizes, int n_in,
                              void* d_out, int out_size)
{
    const float* x    = (const float*)d_in[0];
    const float* pm   = (const float*)d_in[1];
    const float* Wqkv = (const float*)d_in[2];
    const float* Wo   = (const float*)d_in[3];
    float* out = (float*)d_out;

    float *qkv_p, *att_p;
    __nv_bfloat16 *xhi, *xlo, *wqh, *wql, *woh, *wol, *ahi, *alo;
    cudaGetSymbolAddress((void**)&qkv_p, g_qkv);
    cudaGetSymbolAddress((void**)&att_p, g_att);
    cudaGetSymbolAddress((void**)&xhi, g_xhi);
    cudaGetSymbolAddress((void**)&xlo, g_xlo);
    cudaGetSymbolAddress((void**)&wqh, g_wqh);
    cudaGetSymbolAddress((void**)&wql, g_wql);
    cudaGetSymbolAddress((void**)&woh, g_woh);
    cudaGetSymbolAddress((void**)&wol, g_wol);
    cudaGetSymbolAddress((void**)&ahi, g_ahi);
    cudaGetSymbolAddress((void**)&alo, g_alo);

    const int M = BB * SS;            // 4096
    const int nx = M * DD;            // 3.1M

    const int attn_smem = (32 * HDIM + HDIM * 161 + 160 * HDIM + 32 * 160 + 160) * (int)sizeof(float);
    static bool attr_done = false;
    if (!attr_done) {
        cudaFuncSetAttribute(attn_kernel,
                             cudaFuncAttributeMaxDynamicSharedMemorySize, attn_smem);
        cudaFuncSetAttribute(gemm_bf16x3_kernel,
                             cudaFuncAttributeMaxDynamicSharedMemorySize, GEMM_SMEM);
        attr_done = true;
    }

    // Input conversions
    split_kernel<<<(nx + 255) / 256, 256>>>(x, xhi, xlo, nx);
    splitT_kernel<<<dim3(3 * DD / 32, DD / 32), dim3(32, 8)>>>(Wqkv, wqh, wql, DD, 3 * DD);
    splitT_kernel<<<dim3(DD / 32, DD / 32), dim3(32, 8)>>>(Wo, woh, wol, DD, DD);

    // 1) QKV projection on tensor cores: (4096 x 768) @ (768 x 2304)
    gemm_bf16x3_kernel<<<dim3(3 * DD / 128, M / 128), 256, GEMM_SMEM>>>(
        xhi, xlo, wqh, wql, qkv_p, M, 3 * DD, DD);

    // 2) Sliding-window attention
    attn_kernel<<<dim3(SS / 32, HH, BB), 256, attn_smem>>>(qkv_p, pm, att_p);

    // 3) Output projection on tensor cores: (4096 x 768) @ (768 x 768)
    split_kernel<<<(nx + 255) / 256, 256>>>(att_p, ahi, alo, nx);
    gemm_bf16x3_kernel<<<dim3(DD / 128, M / 128), 256, GEMM_SMEM>>>(
        ahi, alo, woh, wol, out, M, DD, DD);
}

// round 6
// speedup vs baseline: 1.4981x; 1.4981x over previous
#include <cuda_runtime.h>
#include <cuda_bf16.h>
#include <cstdint>
#include <math.h>

// Problem constants
#define BB   2
#define SS   2048
#define DD   768
#define HH   12
#define HDIM 64
#define HALFW 64
#define NEGV -1000000000.0f

// ---------------------------------------------------------------------------
// Scratch (no cudaMalloc allowed)
// ---------------------------------------------------------------------------
__device__ float g_qkv[BB * SS * 3 * DD];            // fp32 qkv  (4096 x 2304)
__device__ float g_att[BB * SS * DD];                // fp32 attn out (4096 x 768)
__device__ __nv_bfloat16 g_xhi[BB * SS * DD];        // x split
__device__ __nv_bfloat16 g_xlo[BB * SS * DD];
__device__ __nv_bfloat16 g_wqh[3 * DD * DD];         // Wqkv^T split (2304 x 768)
__device__ __nv_bfloat16 g_wql[3 * DD * DD];
__device__ __nv_bfloat16 g_woh[DD * DD];             // Wo^T split (768 x 768)
__device__ __nv_bfloat16 g_wol[DD * DD];
__device__ __nv_bfloat16 g_ahi[BB * SS * DD];        // att split
__device__ __nv_bfloat16 g_alo[BB * SS * DD];

// ---------------------------------------------------------------------------
// Split / transpose-split conversion kernels
// ---------------------------------------------------------------------------
__global__ __launch_bounds__(256) void split_kernel(
    const float* __restrict__ in, __nv_bfloat16* __restrict__ hi,
    __nv_bfloat16* __restrict__ lo, int n)
{
    int i = blockIdx.x * 256 + threadIdx.x;
    if (i < n) {
        float v = in[i];
        __nv_bfloat16 h = __float2bfloat16(v);
        hi[i] = h;
        lo[i] = __float2bfloat16(v - __bfloat162float(h));
    }
}

// in[K x N] -> hiT/loT [N x K]
__global__ __launch_bounds__(256) void splitT_kernel(
    const float* __restrict__ in, __nv_bfloat16* __restrict__ hiT,
    __nv_bfloat16* __restrict__ loT, int K, int N)
{
    __shared__ float t[32][33];
    const int k0 = blockIdx.y * 32, n0 = blockIdx.x * 32;
    const int tx = threadIdx.x, ty = threadIdx.y;   // 32 x 8
    #pragma unroll
    for (int i = 0; i < 32; i += 8)
        t[ty + i][tx] = in[(size_t)(k0 + ty + i) * N + n0 + tx];
    __syncthreads();
    #pragma unroll
    for (int i = 0; i < 32; i += 8) {
        float v = t[tx][ty + i];
        __nv_bfloat16 h = __float2bfloat16(v);
        size_t o = (size_t)(n0 + ty + i) * K + k0 + tx;
        hiT[o] = h;
        loT[o] = __float2bfloat16(v - __bfloat162float(h));
    }
}

// ---------------------------------------------------------------------------
// bf16x3 mma.sync GEMM with cp.async double buffering + ldmatrix.
// C[M,N] = A[M,K] @ Bt[N,K]^T, fp32 accumulate.
// Block tile 128x128x32, 8 warps (2m x 4n), warp tile 64x32 via m16n8k16.
// M%128==0, N%128==0, K%32==0.
// ---------------------------------------------------------------------------
#define SMS 40                                  // smem row stride, bf16 elems
#define TILE_BYTES (128 * SMS * 2)              // 10240
#define STAGE_BYTES (4 * TILE_BYTES)            // 40960 (Ah, Al, Bh, Bl)
#define GEMM_SMEM (2 * STAGE_BYTES)             // 81920

__device__ __forceinline__ uint32_t smem_u32(const void* p) {
    uint32_t a;
    asm("{ .reg .u64 t; cvta.to.shared.u64 t, %1; cvt.u32.u64 %0, t; }"
        : "=r"(a) : "l"(p));
    return a;
}

__device__ __forceinline__ void cp_async16(uint32_t dst, const void* src) {
    asm volatile("cp.async.cg.shared.global [%0], [%1], 16;" :: "r"(dst), "l"(src));
}

#define CP_COMMIT() asm volatile("cp.async.commit_group;" ::: "memory")
#define CP_WAIT1()  asm volatile("cp.async.wait_group 1;" ::: "memory")

#define LDSM_X4(r0, r1, r2, r3, addr) \
    asm volatile("ldmatrix.sync.aligned.m8n8.x4.shared.b16 {%0,%1,%2,%3}, [%4];" \
                 : "=r"(r0), "=r"(r1), "=r"(r2), "=r"(r3) : "r"(addr))
#define LDSM_X2(r0, r1, addr) \
    asm volatile("ldmatrix.sync.aligned.m8n8.x2.shared.b16 {%0,%1}, [%2];" \
                 : "=r"(r0), "=r"(r1) : "r"(addr))

__device__ __forceinline__ void mma16816(float* c, const uint32_t* a, const uint32_t* b)
{
    asm volatile(
        "mma.sync.aligned.m16n8k16.row.col.f32.bf16.bf16.f32 "
        "{%0,%1,%2,%3}, {%4,%5,%6,%7}, {%8,%9}, {%0,%1,%2,%3};"
        : "+f"(c[0]), "+f"(c[1]), "+f"(c[2]), "+f"(c[3])
        : "r"(a[0]), "r"(a[1]), "r"(a[2]), "r"(a[3]), "r"(b[0]), "r"(b[1]));
}

__global__ __launch_bounds__(256) void gemm_bf16x3_kernel(
    const __nv_bfloat16* __restrict__ Ahi, const __nv_bfloat16* __restrict__ Alo,
    const __nv_bfloat16* __restrict__ Bthi, const __nv_bfloat16* __restrict__ Btlo,
    float* __restrict__ C, int M, int N, int K)
{
    extern __shared__ __align__(128) char smem[];
    const uint32_t smem_base = smem_u32(smem);

    const int tid = threadIdx.x;
    const int wid = tid >> 5, lane = tid & 31;
    const int g = lane >> 2, tg = lane & 3;
    const int wm = wid >> 2, wn = wid & 3;        // 2 x 4 warp grid
    const int mbase = wm * 64, nbase = wn * 32;
    const int bm = blockIdx.y * 128, bn = blockIdx.x * 128;

    const __nv_bfloat16* srcs[4] = {
        Ahi + (size_t)bm * K, Alo + (size_t)bm * K,
        Bthi + (size_t)bn * K, Btlo + (size_t)bn * K };

    const int niter = K >> 5;

    // global/smem staging coords: per tile 2 chunks/thread (rows lr0, lr0+64)
    const int lr0 = tid >> 2, lq = tid & 3;
    const uint32_t st_off = (uint32_t)(lr0 * SMS + lq * 8) * 2;

    // ldmatrix lane address components
    const uint32_t a_lane = (uint32_t)((lane & 15) * (SMS * 2) + ((lane >> 4) << 4));
    const uint32_t b_lane = (uint32_t)((lane & 7) * (SMS * 2) + (((lane >> 3) & 1) << 4));

    float acc[4][4][4];
    #pragma unroll
    for (int i = 0; i < 4; i++)
        #pragma unroll
        for (int j = 0; j < 4; j++)
            #pragma unroll
            for (int c = 0; c < 4; c++) acc[i][j][c] = 0.f;

    // ---- prologue: stages 0 and 1 ----
    #pragma unroll
    for (int p = 0; p < 2; p++) {
        if (p < niter) {
            const int k0 = p << 5;
            const uint32_t sb = smem_base + (uint32_t)p * STAGE_BYTES;
            #pragma unroll
            for (int t = 0; t < 4; t++) {
                const __nv_bfloat16* s = srcs[t] + k0 + lq * 8;
                uint32_t d = sb + (uint32_t)t * TILE_BYTES + st_off;
                cp_async16(d, s + (size_t)lr0 * K);
                cp_async16(d + 64 * SMS * 2, s + (size_t)(lr0 + 64) * K);
            }
        }
        CP_COMMIT();
    }

    for (int it = 0; it < niter; it++) {
        CP_WAIT1();
        __syncthreads();

        const uint32_t sb = smem_base + (uint32_t)(it & 1) * STAGE_BYTES;
        const uint32_t aAh = sb + a_lane;
        const uint32_t aAl = sb + TILE_BYTES + a_lane;
        const uint32_t aBh = sb + 2 * TILE_BYTES + b_lane;
        const uint32_t aBl = sb + 3 * TILE_BYTES + b_lane;

        #pragma unroll
        for (int kk = 0; kk < 32; kk += 16) {
            uint32_t ah[4][4], al[4][4], bh[4][2], bl[4][2];
            #pragma unroll
            for (int mt = 0; mt < 4; mt++) {
                const uint32_t ro = (uint32_t)((mbase + mt * 16) * (SMS * 2) + kk * 2);
                LDSM_X4(ah[mt][0], ah[mt][1], ah[mt][2], ah[mt][3], aAh + ro);
                LDSM_X4(al[mt][0], al[mt][1], al[mt][2], al[mt][3], aAl + ro);
            }
            #pragma unroll
            for (int nt = 0; nt < 4; nt++) {
                const uint32_t ro = (uint32_t)((nbase + nt * 8) * (SMS * 2) + kk * 2);
                LDSM_X2(bh[nt][0], bh[nt][1], aBh + ro);
                LDSM_X2(bl[nt][0], bl[nt][1], aBl + ro);
            }
            #pragma unroll
            for (int mt = 0; mt < 4; mt++)
                #pragma unroll
                for (int nt = 0; nt < 4; nt++)
                    mma16816(acc[mt][nt], ah[mt], bh[nt]);
            #pragma unroll
            for (int mt = 0; mt < 4; mt++)
                #pragma unroll
                for (int nt = 0; nt < 4; nt++)
                    mma16816(acc[mt][nt], ah[mt], bl[nt]);
            #pragma unroll
            for (int mt = 0; mt < 4; mt++)
                #pragma unroll
                for (int nt = 0; nt < 4; nt++)
                    mma16816(acc[mt][nt], al[mt], bh[nt]);
        }
        __syncthreads();

        // issue stage it+2 into the buffer just consumed
        const int nx = it + 2;
        if (nx < niter) {
            const int k0 = nx << 5;
            const uint32_t db = smem_base + (uint32_t)(nx & 1) * STAGE_BYTES;
            #pragma unroll
            for (int t = 0; t < 4; t++) {
                const __nv_bfloat16* s = srcs[t] + k0 + lq * 8;
                uint32_t d = db + (uint32_t)t * TILE_BYTES + st_off;
                cp_async16(d, s + (size_t)lr0 * K);
                cp_async16(d + 64 * SMS * 2, s + (size_t)(lr0 + 64) * K);
            }
        }
        CP_COMMIT();
    }

    // Epilogue: direct fp32 stores (float2 per fragment half)
    #pragma unroll
    for (int mt = 0; mt < 4; mt++) {
        #pragma unroll
        for (int nt = 0; nt < 4; nt++) {
            const int row = bm + mbase + mt * 16 + g;
            const int col = bn + nbase + nt * 8 + tg * 2;
            float2 v0; v0.x = acc[mt][nt][0]; v0.y = acc[mt][nt][1];
            float2 v1; v1.x = acc[mt][nt][2]; v1.y = acc[mt][nt][3];
            *(float2*)&C[(size_t)row * N + col] = v0;
            *(float2*)&C[(size_t)(row + 8) * N + col] = v1;
        }
    }
}

// ---------------------------------------------------------------------------
// Sliding-window attention (unchanged)
// ---------------------------------------------------------------------------
__global__ __launch_bounds__(256) void attn_kernel(
    const float* __restrict__ qkv, const float* __restrict__ pmask,
    float* __restrict__ out)
{
    constexpr int QC = 32, KMAX = 160, KPAD = 161;
    extern __shared__ float sm[];
    float* Qs = sm;
    float* Ks = Qs + QC * HDIM;
    float* Vs = Ks + HDIM * KPAD;
    float* Ss = Vs + KMAX * HDIM;
    float* Pn = Ss + QC * KMAX;

    const int chunk = blockIdx.x, h = blockIdx.y, b = blockIdx.z;
    const int qbase = chunk * QC;
    const int k0   = max(0, qbase - HALFW);
    const int kend = min(SS, qbase + QC + HALFW);
    const int kN   = kend - k0;
    const int tid  = threadIdx.x;

    for (int idx = tid; idx < QC * HDIM; idx += 256) {
        int q = idx >> 6, d = idx & 63;
        Qs[q * HDIM + d] = qkv[((size_t)(b * SS + qbase + q)) * (3 * DD) + h * HDIM + d];
    }
    for (int idx = tid; idx < kN * HDIM; idx += 256) {
        int k = idx >> 6, d = idx & 63;
        size_t base = ((size_t)(b * SS + k0 + k)) * (3 * DD) + h * HDIM + d;
        Ks[d * KPAD + k] = qkv[base + DD];
        Vs[k * HDIM + d] = qkv[base + 2 * DD];
    }
    for (int k = tid; k < kN; k += 256)
        Pn[k] = (1.0f - pmask[b * SS + k0 + k]) * NEGV;
    __syncthreads();

    const int warp = tid >> 5, lane = tid & 31;
    const int qrow = warp * 4;

    float acc[4][5];
    #pragma unroll
    for (int i = 0; i < 4; i++)
        #pragma unroll
        for (int j = 0; j < 5; j++) acc[i][j] = 0.f;

    #pragma unroll 4
    for (int d = 0; d < HDIM; d++) {
        float aq[4];
        #pragma unroll
        for (int i = 0; i < 4; i++) aq[i] = Qs[(qrow + i) * HDIM + d];
        float kv[5];
        #pragma unroll
        for (int j = 0; j < 5; j++) kv[j] = Ks[d * KPAD + lane * 5 + j];
        #pragma unroll
        for (int i = 0; i < 4; i++)
            #pragma unroll
            for (int j = 0; j < 5; j++)
                acc[i][j] = fmaf(aq[i], kv[j], acc[i][j]);
    }

    const float scale = 0.125f;
    #pragma unroll
    for (int i = 0; i < 4; i++) {
        int gq = qbase + qrow + i;
        #pragma unroll
        for (int j = 0; j < 5; j++) {
            int k = lane * 5 + j;
            if (k < kN) {
                int gk = k0 + k;
                int dd = gq - gk; if (dd < 0) dd = -dd;
                float s = (dd <= HALFW) ? (acc[i][j] * scale + Pn[k]) : -1e30f;
                Ss[(qrow + i) * KMAX + k] = s;
            }
        }
    }
    __syncwarp();

    #pragma unroll
    for (int i = 0; i < 4; i++) {
        float* row = &Ss[(qrow + i) * KMAX];
        float m = -1e30f;
        for (int k = lane; k < kN; k += 32) m = fmaxf(m, row[k]);
        #pragma unroll
        for (int o = 16; o; o >>= 1) m = fmaxf(m, __shfl_xor_sync(0xffffffffu, m, o));
        float sum = 0.f;
        for (int k = lane; k < kN; k += 32) {
            float e = __expf(row[k] - m);
            row[k] = e;
            sum += e;
        }
        #pragma unroll
        for (int o = 16; o; o >>= 1) sum += __shfl_xor_sync(0xffffffffu, sum, o);
        float inv = 1.f / sum;
        for (int k = lane; k < kN; k += 32) row[k] *= inv;
    }
    __syncwarp();

    float o[4][2];
    #pragma unroll
    for (int i = 0; i < 4; i++) { o[i][0] = 0.f; o[i][1] = 0.f; }
    const int d0 = lane * 2;
    for (int k = 0; k < kN; k++) {
        float2 v = *(const float2*)&Vs[k * HDIM + d0];
        #pragma unroll
        for (int i = 0; i < 4; i++) {
            float p = Ss[(qrow + i) * KMAX + k];
            o[i][0] = fmaf(p, v.x, o[i][0]);
            o[i][1] = fmaf(p, v.y, o[i][1]);
        }
    }
    #pragma unroll
    for (int i = 0; i < 4; i++) {
        int gq = qbase + qrow + i;
        float2 r; r.x = o[i][0]; r.y = o[i][1];
        *(float2*)&out[((size_t)(b * SS + gq)) * DD + h * HDIM + d0] = r;
    }
}

// ---------------------------------------------------------------------------
extern "C" void kernel_launch(void* const* d_in, const int* in_sizes, int n_in,
                              void* d_out, int out_size)
{
    const float* x    = (const float*)d_in[0];
    const float* pm   = (const float*)d_in[1];
    const float* Wqkv = (const float*)d_in[2];
    const float* Wo   = (const float*)d_in[3];
    float* out = (float*)d_out;

    float *qkv_p, *att_p;
    __nv_bfloat16 *xhi, *xlo, *wqh, *wql, *woh, *wol, *ahi, *alo;
    cudaGetSymbolAddress((void**)&qkv_p, g_qkv);
    cudaGetSymbolAddress((void**)&att_p, g_att);
    cudaGetSymbolAddress((void**)&xhi, g_xhi);
    cudaGetSymbolAddress((void**)&xlo, g_xlo);
    cudaGetSymbolAddress((void**)&wqh, g_wqh);
    cudaGetSymbolAddress((void**)&wql, g_wql);
    cudaGetSymbolAddress((void**)&woh, g_woh);
    cudaGetSymbolAddress((void**)&wol, g_wol);
    cudaGetSymbolAddress((void**)&ahi, g_ahi);
    cudaGetSymbolAddress((void**)&alo, g_alo);

    const int M = BB * SS;            // 4096
    const int nx = M * DD;            // 3.1M

    const int attn_smem = (32 * HDIM + HDIM * 161 + 160 * HDIM + 32 * 160 + 160) * (int)sizeof(float);
    static bool attr_done = false;
    if (!attr_done) {
        cudaFuncSetAttribute(attn_kernel,
                             cudaFuncAttributeMaxDynamicSharedMemorySize, attn_smem);
        cudaFuncSetAttribute(gemm_bf16x3_kernel,
                             cudaFuncAttributeMaxDynamicSharedMemorySize, GEMM_SMEM);
        attr_done = true;
    }

    // Input conversions
    split_kernel<<<(nx + 255) / 256, 256>>>(x, xhi, xlo, nx);
    splitT_kernel<<<dim3(3 * DD / 32, DD / 32), dim3(32, 8)>>>(Wqkv, wqh, wql, DD, 3 * DD);
    splitT_kernel<<<dim3(DD / 32, DD / 32), dim3(32, 8)>>>(Wo, woh, wol, DD, DD);

    // 1) QKV projection on tensor cores: (4096 x 768) @ (768 x 2304)
    gemm_bf16x3_kernel<<<dim3(3 * DD / 128, M / 128), 256, GEMM_SMEM>>>(
        xhi, xlo, wqh, wql, qkv_p, M, 3 * DD, DD);

    // 2) Sliding-window attention
    attn_kernel<<<dim3(SS / 32, HH, BB), 256, attn_smem>>>(qkv_p, pm, att_p);

    // 3) Output projection on tensor cores: (4096 x 768) @ (768 x 768)
    split_kernel<<<(nx + 255) / 256, 256>>>(att_p, ahi, alo, nx);
    gemm_bf16x3_kernel<<<dim3(DD / 128, M / 128), 256, GEMM_SMEM>>>(
        ahi, alo, woh, wol, out, M, DD, DD);
}

// round 7
// speedup vs baseline: 1.8977x; 1.2668x over previous
#include <cuda_runtime.h>
#include <cuda_bf16.h>
#include <cstdint>
#include <math.h>

// Problem constants
#define BB   2
#define SS   2048
#define DD   768
#define HH   12
#define HDIM 64
#define HALFW 64
#define NEGV -1000000000.0f

// ---------------------------------------------------------------------------
// Scratch (no cudaMalloc allowed)
// ---------------------------------------------------------------------------
__device__ float g_qkv[BB * SS * 3 * DD];            // fp32 qkv  (4096 x 2304)
__device__ __nv_bfloat16 g_xhi[BB * SS * DD];        // x split
__device__ __nv_bfloat16 g_xlo[BB * SS * DD];
__device__ __nv_bfloat16 g_wqh[3 * DD * DD];         // Wqkv^T split (2304 x 768)
__device__ __nv_bfloat16 g_wql[3 * DD * DD];
__device__ __nv_bfloat16 g_woh[DD * DD];             // Wo^T split (768 x 768)
__device__ __nv_bfloat16 g_wol[DD * DD];
__device__ __nv_bfloat16 g_ahi[BB * SS * DD];        // attn out split (written by attn)
__device__ __nv_bfloat16 g_alo[BB * SS * DD];

// ---------------------------------------------------------------------------
// Common helpers
// ---------------------------------------------------------------------------
__device__ __forceinline__ uint32_t smem_u32(const void* p) {
    uint32_t a;
    asm("{ .reg .u64 t; cvta.to.shared.u64 t, %1; cvt.u32.u64 %0, t; }"
        : "=r"(a) : "l"(p));
    return a;
}

__device__ __forceinline__ void cp_async16(uint32_t dst, const void* src) {
    asm volatile("cp.async.cg.shared.global [%0], [%1], 16;" :: "r"(dst), "l"(src));
}
#define CP_COMMIT() asm volatile("cp.async.commit_group;" ::: "memory")
#define CP_WAIT1()  asm volatile("cp.async.wait_group 1;" ::: "memory")

#define LDSM_X4(r0, r1, r2, r3, addr) \
    asm volatile("ldmatrix.sync.aligned.m8n8.x4.shared.b16 {%0,%1,%2,%3}, [%4];" \
                 : "=r"(r0), "=r"(r1), "=r"(r2), "=r"(r3) : "r"(addr))
#define LDSM_X2(r0, r1, addr) \
    asm volatile("ldmatrix.sync.aligned.m8n8.x2.shared.b16 {%0,%1}, [%2];" \
                 : "=r"(r0), "=r"(r1) : "r"(addr))
#define LDSM_X2T(r0, r1, addr) \
    asm volatile("ldmatrix.sync.aligned.m8n8.x2.trans.shared.b16 {%0,%1}, [%2];" \
                 : "=r"(r0), "=r"(r1) : "r"(addr))

__device__ __forceinline__ void mma16816(float* c, const uint32_t* a, const uint32_t* b)
{
    asm volatile(
        "mma.sync.aligned.m16n8k16.row.col.f32.bf16.bf16.f32 "
        "{%0,%1,%2,%3}, {%4,%5,%6,%7}, {%8,%9}, {%0,%1,%2,%3};"
        : "+f"(c[0]), "+f"(c[1]), "+f"(c[2]), "+f"(c[3])
        : "r"(a[0]), "r"(a[1]), "r"(a[2]), "r"(a[3]), "r"(b[0]), "r"(b[1]));
}

__device__ __forceinline__ void split2(float a, float b, uint32_t& hi, uint32_t& lo)
{
    __nv_bfloat16 ha = __float2bfloat16(a), hb = __float2bfloat16(b);
    __nv_bfloat16 la = __float2bfloat16(a - __bfloat162float(ha));
    __nv_bfloat16 lb = __float2bfloat16(b - __bfloat162float(hb));
    hi = ((uint32_t)__bfloat16_as_ushort(hb) << 16) | (uint32_t)__bfloat16_as_ushort(ha);
    lo = ((uint32_t)__bfloat16_as_ushort(lb) << 16) | (uint32_t)__bfloat16_as_ushort(la);
}

// ---------------------------------------------------------------------------
// Split / transpose-split conversion kernels
// ---------------------------------------------------------------------------
__global__ __launch_bounds__(256) void split_kernel(
    const float* __restrict__ in, __nv_bfloat16* __restrict__ hi,
    __nv_bfloat16* __restrict__ lo, int n)
{
    int i = blockIdx.x * 256 + threadIdx.x;
    if (i < n) {
        float v = in[i];
        __nv_bfloat16 h = __float2bfloat16(v);
        hi[i] = h;
        lo[i] = __float2bfloat16(v - __bfloat162float(h));
    }
}

__global__ __launch_bounds__(256) void splitT_kernel(
    const float* __restrict__ in, __nv_bfloat16* __restrict__ hiT,
    __nv_bfloat16* __restrict__ loT, int K, int N)
{
    __shared__ float t[32][33];
    const int k0 = blockIdx.y * 32, n0 = blockIdx.x * 32;
    const int tx = threadIdx.x, ty = threadIdx.y;   // 32 x 8
    #pragma unroll
    for (int i = 0; i < 32; i += 8)
        t[ty + i][tx] = in[(size_t)(k0 + ty + i) * N + n0 + tx];
    __syncthreads();
    #pragma unroll
    for (int i = 0; i < 32; i += 8) {
        float v = t[tx][ty + i];
        __nv_bfloat16 h = __float2bfloat16(v);
        size_t o = (size_t)(n0 + ty + i) * K + k0 + tx;
        hiT[o] = h;
        loT[o] = __float2bfloat16(v - __bfloat162float(h));
    }
}

// ---------------------------------------------------------------------------
// bf16x3 mma.sync GEMM (unchanged from round 6)
// ---------------------------------------------------------------------------
#define SMS 40
#define TILE_BYTES (128 * SMS * 2)
#define STAGE_BYTES (4 * TILE_BYTES)
#define GEMM_SMEM (2 * STAGE_BYTES)

__global__ __launch_bounds__(256) void gemm_bf16x3_kernel(
    const __nv_bfloat16* __restrict__ Ahi, const __nv_bfloat16* __restrict__ Alo,
    const __nv_bfloat16* __restrict__ Bthi, const __nv_bfloat16* __restrict__ Btlo,
    float* __restrict__ C, int M, int N, int K)
{
    extern __shared__ __align__(128) char smem[];
    const uint32_t smem_base = smem_u32(smem);

    const int tid = threadIdx.x;
    const int wid = tid >> 5, lane = tid & 31;
    const int g = lane >> 2, tg = lane & 3;
    const int wm = wid >> 2, wn = wid & 3;
    const int mbase = wm * 64, nbase = wn * 32;
    const int bm = blockIdx.y * 128, bn = blockIdx.x * 128;

    const __nv_bfloat16* srcs[4] = {
        Ahi + (size_t)bm * K, Alo + (size_t)bm * K,
        Bthi + (size_t)bn * K, Btlo + (size_t)bn * K };

    const int niter = K >> 5;
    const int lr0 = tid >> 2, lq = tid & 3;
    const uint32_t st_off = (uint32_t)(lr0 * SMS + lq * 8) * 2;

    const uint32_t a_lane = (uint32_t)((lane & 15) * (SMS * 2) + ((lane >> 4) << 4));
    const uint32_t b_lane = (uint32_t)((lane & 7) * (SMS * 2) + (((lane >> 3) & 1) << 4));

    float acc[4][4][4];
    #pragma unroll
    for (int i = 0; i < 4; i++)
        #pragma unroll
        for (int j = 0; j < 4; j++)
            #pragma unroll
            for (int c = 0; c < 4; c++) acc[i][j][c] = 0.f;

    #pragma unroll
    for (int p = 0; p < 2; p++) {
        if (p < niter) {
            const int k0 = p << 5;
            const uint32_t sb = smem_base + (uint32_t)p * STAGE_BYTES;
            #pragma unroll
            for (int t = 0; t < 4; t++) {
                const __nv_bfloat16* s = srcs[t] + k0 + lq * 8;
                uint32_t d = sb + (uint32_t)t * TILE_BYTES + st_off;
                cp_async16(d, s + (size_t)lr0 * K);
                cp_async16(d + 64 * SMS * 2, s + (size_t)(lr0 + 64) * K);
            }
        }
        CP_COMMIT();
    }

    for (int it = 0; it < niter; it++) {
        CP_WAIT1();
        __syncthreads();

        const uint32_t sb = smem_base + (uint32_t)(it & 1) * STAGE_BYTES;
        const uint32_t aAh = sb + a_lane;
        const uint32_t aAl = sb + TILE_BYTES + a_lane;
        const uint32_t aBh = sb + 2 * TILE_BYTES + b_lane;
        const uint32_t aBl = sb + 3 * TILE_BYTES + b_lane;

        #pragma unroll
        for (int kk = 0; kk < 32; kk += 16) {
            uint32_t ah[4][4], al[4][4], bh[4][2], bl[4][2];
            #pragma unroll
            for (int mt = 0; mt < 4; mt++) {
                const uint32_t ro = (uint32_t)((mbase + mt * 16) * (SMS * 2) + kk * 2);
                LDSM_X4(ah[mt][0], ah[mt][1], ah[mt][2], ah[mt][3], aAh + ro);
                LDSM_X4(al[mt][0], al[mt][1], al[mt][2], al[mt][3], aAl + ro);
            }
            #pragma unroll
            for (int nt = 0; nt < 4; nt++) {
                const uint32_t ro = (uint32_t)((nbase + nt * 8) * (SMS * 2) + kk * 2);
                LDSM_X2(bh[nt][0], bh[nt][1], aBh + ro);
                LDSM_X2(bl[nt][0], bl[nt][1], aBl + ro);
            }
            #pragma unroll
            for (int mt = 0; mt < 4; mt++)
                #pragma unroll
                for (int nt = 0; nt < 4; nt++)
                    mma16816(acc[mt][nt], ah[mt], bh[nt]);
            #pragma unroll
            for (int mt = 0; mt < 4; mt++)
                #pragma unroll
                for (int nt = 0; nt < 4; nt++)
                    mma16816(acc[mt][nt], ah[mt], bl[nt]);
            #pragma unroll
            for (int mt = 0; mt < 4; mt++)
                #pragma unroll
                for (int nt = 0; nt < 4; nt++)
                    mma16816(acc[mt][nt], al[mt], bh[nt]);
        }
        __syncthreads();

        const int nx = it + 2;
        if (nx < niter) {
            const int k0 = nx << 5;
            const uint32_t db = smem_base + (uint32_t)(nx & 1) * STAGE_BYTES;
            #pragma unroll
            for (int t = 0; t < 4; t++) {
                const __nv_bfloat16* s = srcs[t] + k0 + lq * 8;
                uint32_t d = db + (uint32_t)t * TILE_BYTES + st_off;
                cp_async16(d, s + (size_t)lr0 * K);
                cp_async16(d + 64 * SMS * 2, s + (size_t)(lr0 + 64) * K);
            }
        }
        CP_COMMIT();
    }

    #pragma unroll
    for (int mt = 0; mt < 4; mt++) {
        #pragma unroll
        for (int nt = 0; nt < 4; nt++) {
            const int row = bm + mbase + mt * 16 + g;
            const int col = bn + nbase + nt * 8 + tg * 2;
            float2 v0; v0.x = acc[mt][nt][0]; v0.y = acc[mt][nt][1];
            float2 v1; v1.x = acc[mt][nt][2]; v1.y = acc[mt][nt][3];
            *(float2*)&C[(size_t)row * N + col] = v0;
            *(float2*)&C[(size_t)(row + 8) * N + col] = v1;
        }
    }
}

// ---------------------------------------------------------------------------
// Tensor-core sliding-window attention (bf16x3), fused output split.
// Block = (qtile 64, head, batch). Keys: fixed 192 window [q0-64, q0+128).
//
// smem map (bytes):
//   KH 0..24576       K hi tile  [192 keys][64 d], 128B rows, SW128 xor
//   KL 24576..49152   K lo tile            (KH/KL reused as PH/PL after ph.1)
//   VH 49152..73728   V hi tile  [192 keys][64 d]
//   VL 73728..98304   V lo tile
//   PN 98304..99072   padding/-inf per key (192 f32)
//   RM 99072..99584   row-max exchange [64][2]
//   RS 99584..100096  row-sum exchange [64][2]
// ---------------------------------------------------------------------------
#define AT_KH 0
#define AT_KL 24576
#define AT_VH 49152
#define AT_VL 73728
#define AT_PN 98304
#define AT_RM 99072
#define AT_RS 99584
#define ATTN_SMEM 100096

__global__ __launch_bounds__(256, 2) void attn_mma_kernel(
    const float* __restrict__ qkv, const float* __restrict__ pmask,
    __nv_bfloat16* __restrict__ ohi, __nv_bfloat16* __restrict__ olo)
{
    extern __shared__ __align__(128) char smem[];
    const uint32_t sb = smem_u32(smem);
    float* PNf = (float*)(smem + AT_PN);
    float* RMf = (float*)(smem + AT_RM);
    float* RSf = (float*)(smem + AT_RS);

    const int qt = blockIdx.x, h = blockIdx.y, b = blockIdx.z;
    const int q0 = qt * 64;
    const int kstart = q0 - 64;                 // key j -> global key kstart + j
    const int tid = threadIdx.x;
    const int wid = tid >> 5, lane = tid & 31;
    const int g = lane >> 2, tg = lane & 3;

    // ---- Q fragments direct from gmem fp32, split to bf16 hi/lo ----
    // phase-1 warp grid: wm1 = wid>>1 (4 m-tiles of 16), wn1 = wid&1 (2 n-halves of 96)
    const int wm1 = wid >> 1, wn1 = wid & 1;
    uint32_t qh[4][4], ql[4][4];
    {
        const float* qr0 = qkv + ((size_t)(b * SS + q0 + wm1 * 16 + g)) * (3 * DD) + h * HDIM;
        const float* qr8 = qr0 + (size_t)8 * (3 * DD);
        #pragma unroll
        for (int ks = 0; ks < 4; ks++) {
            float2 x0 = *(const float2*)(qr0 + ks * 16 + tg * 2);
            float2 x1 = *(const float2*)(qr8 + ks * 16 + tg * 2);
            float2 x2 = *(const float2*)(qr0 + ks * 16 + 8 + tg * 2);
            float2 x3 = *(const float2*)(qr8 + ks * 16 + 8 + tg * 2);
            split2(x0.x, x0.y, qh[ks][0], ql[ks][0]);
            split2(x1.x, x1.y, qh[ks][1], ql[ks][1]);
            split2(x2.x, x2.y, qh[ks][2], ql[ks][2]);
            split2(x3.x, x3.y, qh[ks][3], ql[ks][3]);
        }
    }

    // ---- stage K/V hi/lo tiles (fp32 -> bf16 split, SW128 swizzle) ----
    for (int idx = tid; idx < 192 * 8; idx += 256) {
        const int key = idx >> 3, u = idx & 7;
        const int gk = kstart + key;
        float4 kv0, kv1, vv0, vv1;
        if (gk >= 0 && gk < SS) {
            const float* base = qkv + ((size_t)(b * SS + gk)) * (3 * DD) + h * HDIM + u * 8;
            kv0 = *(const float4*)(base + DD);
            kv1 = *(const float4*)(base + DD + 4);
            vv0 = *(const float4*)(base + 2 * DD);
            vv1 = *(const float4*)(base + 2 * DD + 4);
        } else {
            kv0 = kv1 = vv0 = vv1 = make_float4(0.f, 0.f, 0.f, 0.f);
        }
        const uint32_t swo = (uint32_t)(key * 128 + ((u * 16) ^ ((key & 7) << 4)));
        uint4 hi4, lo4;
        split2(kv0.x, kv0.y, hi4.x, lo4.x);
        split2(kv0.z, kv0.w, hi4.y, lo4.y);
        split2(kv1.x, kv1.y, hi4.z, lo4.z);
        split2(kv1.z, kv1.w, hi4.w, lo4.w);
        *(uint4*)(smem + AT_KH + swo) = hi4;
        *(uint4*)(smem + AT_KL + swo) = lo4;
        split2(vv0.x, vv0.y, hi4.x, lo4.x);
        split2(vv0.z, vv0.w, hi4.y, lo4.y);
        split2(vv1.x, vv1.y, hi4.z, lo4.z);
        split2(vv1.z, vv1.w, hi4.w, lo4.w);
        *(uint4*)(smem + AT_VH + swo) = hi4;
        *(uint4*)(smem + AT_VL + swo) = lo4;
    }
    for (int j = tid; j < 192; j += 256) {
        const int gk = kstart + j;
        PNf[j] = (gk >= 0 && gk < SS) ? (1.0f - pmask[b * SS + gk]) * NEGV : -1e30f;
    }
    __syncthreads();

    // ---- phase 1: S = Q K^T (bf16x3), acc in registers ----
    float acc[12][4];
    #pragma unroll
    for (int nt = 0; nt < 12; nt++)
        #pragma unroll
        for (int c = 0; c < 4; c++) acc[nt][c] = 0.f;

    #pragma unroll
    for (int ks = 0; ks < 4; ks++) {
        #pragma unroll
        for (int nt = 0; nt < 12; nt++) {
            const int brow = wn1 * 96 + nt * 8 + (lane & 7);
            const uint32_t bo = (uint32_t)(brow * 128 +
                ((ks * 32 + ((lane >> 3) & 1) * 16) ^ ((lane & 7) << 4)));
            uint32_t bh[2], bl[2];
            LDSM_X2(bh[0], bh[1], sb + AT_KH + bo);
            LDSM_X2(bl[0], bl[1], sb + AT_KL + bo);
            mma16816(acc[nt], qh[ks], bh);
            mma16816(acc[nt], qh[ks], bl);
            mma16816(acc[nt], ql[ks], bh);
        }
    }

    // ---- mask + scale in registers ----
    const int r0 = wm1 * 16 + g;        // local q rows r0, r0+8
    const int r1 = r0 + 8;
    #pragma unroll
    for (int nt = 0; nt < 12; nt++) {
        const int j0 = wn1 * 96 + nt * 8 + tg * 2;
        #pragma unroll
        for (int e = 0; e < 4; e++) {
            const int j = j0 + (e & 1);
            const int rr = (e < 2) ? r0 : r1;
            const int diff = j - rr;
            acc[nt][e] = (diff >= 0 && diff <= 128)
                       ? acc[nt][e] * 0.125f + PNf[j] : -1e30f;
        }
    }

    // ---- softmax: register + shuffle + cross-warp smem exchange ----
    float m0 = -1e30f, m1 = -1e30f;
    #pragma unroll
    for (int nt = 0; nt < 12; nt++) {
        m0 = fmaxf(m0, fmaxf(acc[nt][0], acc[nt][1]));
        m1 = fmaxf(m1, fmaxf(acc[nt][2], acc[nt][3]));
    }
    #pragma unroll
    for (int o = 1; o <= 2; o <<= 1) {
        m0 = fmaxf(m0, __shfl_xor_sync(0xffffffffu, m0, o));
        m1 = fmaxf(m1, __shfl_xor_sync(0xffffffffu, m1, o));
    }
    if (tg == 0) { RMf[r0 * 2 + wn1] = m0; RMf[r1 * 2 + wn1] = m1; }
    __syncthreads();
    m0 = fmaxf(RMf[r0 * 2], RMf[r0 * 2 + 1]);
    m1 = fmaxf(RMf[r1 * 2], RMf[r1 * 2 + 1]);

    float s0 = 0.f, s1 = 0.f;
    #pragma unroll
    for (int nt = 0; nt < 12; nt++) {
        acc[nt][0] = __expf(acc[nt][0] - m0);
        acc[nt][1] = __expf(acc[nt][1] - m0);
        acc[nt][2] = __expf(acc[nt][2] - m1);
        acc[nt][3] = __expf(acc[nt][3] - m1);
        s0 += acc[nt][0] + acc[nt][1];
        s1 += acc[nt][2] + acc[nt][3];
    }
    #pragma unroll
    for (int o = 1; o <= 2; o <<= 1) {
        s0 += __shfl_xor_sync(0xffffffffu, s0, o);
        s1 += __shfl_xor_sync(0xffffffffu, s1, o);
    }
    if (tg == 0) { RSf[r0 * 2 + wn1] = s0; RSf[r1 * 2 + wn1] = s1; }
    __syncthreads();
    const float inv0 = 1.f / (RSf[r0 * 2] + RSf[r0 * 2 + 1]);
    const float inv1 = 1.f / (RSf[r1 * 2] + RSf[r1 * 2 + 1]);

    // ---- write P hi/lo (bf16) over the dead K region ----
    // P layout: [64 q rows][192 keys], 384B rows, 16B-unit XOR by (row&7)<<4
    #pragma unroll
    for (int nt = 0; nt < 12; nt++) {
        const int j0 = wn1 * 96 + nt * 8 + tg * 2;
        uint32_t hi, lo;
        split2(acc[nt][0] * inv0, acc[nt][1] * inv0, hi, lo);
        uint32_t o0 = (uint32_t)(r0 * 384 + ((j0 * 2) ^ ((r0 & 7) << 4)));
        *(uint32_t*)(smem + AT_KH + o0) = hi;
        *(uint32_t*)(smem + AT_KL + o0) = lo;
        split2(acc[nt][2] * inv1, acc[nt][3] * inv1, hi, lo);
        uint32_t o1 = (uint32_t)(r1 * 384 + ((j0 * 2) ^ ((r1 & 7) << 4)));
        *(uint32_t*)(smem + AT_KH + o1) = hi;
        *(uint32_t*)(smem + AT_KL + o1) = lo;
    }
    __syncthreads();

    // ---- phase 2: O = P V (bf16x3) ----
    // warp grid: wm3 = wid>>1 (m tiles of 16), wn3 = wid&1 (n halves of 32)
    const int wm3 = wm1, wn3 = wn1;
    float oacc[4][4];
    #pragma unroll
    for (int nt = 0; nt < 4; nt++)
        #pragma unroll
        for (int c = 0; c < 4; c++) oacc[nt][c] = 0.f;

    #pragma unroll
    for (int ks = 0; ks < 12; ks++) {
        const int prow = wm3 * 16 + (lane & 15);
        const uint32_t po = (uint32_t)(prow * 384 +
            ((ks * 32 + (lane >> 4) * 16) ^ ((prow & 7) << 4)));
        uint32_t ph[4], pl[4];
        LDSM_X4(ph[0], ph[1], ph[2], ph[3], sb + AT_KH + po);
        LDSM_X4(pl[0], pl[1], pl[2], pl[3], sb + AT_KL + po);
        #pragma unroll
        for (int nt = 0; nt < 4; nt++) {
            const int vrow = ks * 16 + (lane & 15);
            const uint32_t vo = (uint32_t)(vrow * 128 +
                (((wn3 * 32 + nt * 8) * 2) ^ ((vrow & 7) << 4)));
            uint32_t vh[2], vl[2];
            LDSM_X2T(vh[0], vh[1], sb + AT_VH + vo);
            LDSM_X2T(vl[0], vl[1], sb + AT_VL + vo);
            mma16816(oacc[nt], ph, vh);
            mma16816(oacc[nt], ph, vl);
            mma16816(oacc[nt], pl, vh);
        }
    }

    // ---- epilogue: write bf16 hi/lo attention output (fused split) ----
    #pragma unroll
    for (int nt = 0; nt < 4; nt++) {
        const int gq0 = q0 + wm3 * 16 + g;
        const int col = h * HDIM + wn3 * 32 + nt * 8 + tg * 2;
        uint32_t hi, lo;
        size_t off = ((size_t)(b * SS + gq0)) * DD + col;
        split2(oacc[nt][0], oacc[nt][1], hi, lo);
        *(uint32_t*)(ohi + off) = hi;
        *(uint32_t*)(olo + off) = lo;
        off += (size_t)8 * DD;
        split2(oacc[nt][2], oacc[nt][3], hi, lo);
        *(uint32_t*)(ohi + off) = hi;
        *(uint32_t*)(olo + off) = lo;
    }
}

// ---------------------------------------------------------------------------
extern "C" void kernel_launch(void* const* d_in, const int* in_sizes, int n_in,
                              void* d_out, int out_size)
{
    const float* x    = (const float*)d_in[0];
    const float* pm   = (const float*)d_in[1];
    const float* Wqkv = (const float*)d_in[2];
    const float* Wo   = (const float*)d_in[3];
    float* out = (float*)d_out;

    float* qkv_p;
    __nv_bfloat16 *xhi, *xlo, *wqh, *wql, *woh, *wol, *ahi, *alo;
    cudaGetSymbolAddress((void**)&qkv_p, g_qkv);
    cudaGetSymbolAddress((void**)&xhi, g_xhi);
    cudaGetSymbolAddress((void**)&xlo, g_xlo);
    cudaGetSymbolAddress((void**)&wqh, g_wqh);
    cudaGetSymbolAddress((void**)&wql, g_wql);
    cudaGetSymbolAddress((void**)&woh, g_woh);
    cudaGetSymbolAddress((void**)&wol, g_wol);
    cudaGetSymbolAddress((void**)&ahi, g_ahi);
    cudaGetSymbolAddress((void**)&alo, g_alo);

    const int M = BB * SS;            // 4096
    const int nx = M * DD;            // 3.1M

    static bool attr_done = false;
    if (!attr_done) {
        cudaFuncSetAttribute(gemm_bf16x3_kernel,
                             cudaFuncAttributeMaxDynamicSharedMemorySize, GEMM_SMEM);
        cudaFuncSetAttribute(attn_mma_kernel,
                             cudaFuncAttributeMaxDynamicSharedMemorySize, ATTN_SMEM);
        attr_done = true;
    }

    // Input conversions
    split_kernel<<<(nx + 255) / 256, 256>>>(x, xhi, xlo, nx);
    splitT_kernel<<<dim3(3 * DD / 32, DD / 32), dim3(32, 8)>>>(Wqkv, wqh, wql, DD, 3 * DD);
    splitT_kernel<<<dim3(DD / 32, DD / 32), dim3(32, 8)>>>(Wo, woh, wol, DD, DD);

    // 1) QKV projection (tensor cores)
    gemm_bf16x3_kernel<<<dim3(3 * DD / 128, M / 128), 256, GEMM_SMEM>>>(
        xhi, xlo, wqh, wql, qkv_p, M, 3 * DD, DD);

    // 2) Sliding-window attention (tensor cores), writes bf16 hi/lo directly
    attn_mma_kernel<<<dim3(SS / 64, HH, BB), 256, ATTN_SMEM>>>(qkv_p, pm, ahi, alo);

    // 3) Output projection (tensor cores)
    gemm_bf16x3_kernel<<<dim3(DD / 128, M / 128), 256, GEMM_SMEM>>>(
        ahi, alo, woh, wol, out, M, DD, DD);
}